// round 4
// baseline (speedup 1.0000x reference)
#include <cuda_runtime.h>
#include <cuda_bf16.h>

// MedianFilter1D: x[16, 64, 16384] fp32, window k=9, zero padding.
// 1024 rows x 16384. Round 4: 16 outputs per thread.
//
// R3 analysis: ALU-time ~10.6us, DRAM-time ~10.7us, kernel 21.3us -> poor
// overlap (one load-wait point per warp, not enough compute per warp to hide
// ~500cyc DRAM latency at 6 warps/SMSP). Fix: 6 front-batched LDG.128 per
// thread (MLP=6), 2x compute per wait point, 8 independent sort cones (ILP).
//
// Median trick: windows o and o+1 share 8 elements. Sort the shared 8
// (Batcher; DCE prunes to the rank-3/4 cone), then
//   median9 = min(max(x_inserted, s3), s4).

#define CE(a, b) { float _lo = fminf(a, b); float _hi = fmaxf(a, b); (a) = _lo; (b) = _hi; }

__device__ __forceinline__ void rank34_of8(
    float a0, float a1, float a2, float a3,
    float a4, float a5, float a6, float a7,
    float& s3, float& s4)
{
    CE(a0, a1) CE(a2, a3) CE(a4, a5) CE(a6, a7)
    CE(a0, a2) CE(a1, a3) CE(a4, a6) CE(a5, a7)
    CE(a1, a2) CE(a5, a6)
    CE(a0, a4) CE(a1, a5) CE(a2, a6) CE(a3, a7)
    CE(a2, a4) CE(a3, a5)
    CE(a1, a2) CE(a3, a4) CE(a5, a6)
    s3 = a3;
    s4 = a4;
}

static constexpr int L    = 16384;
static constexpr int ROWS = 16 * 64;            // 1024
static constexpr int OPT  = 16;                 // outputs per thread
static constexpr int TPB  = 256;
static constexpr int THREADS_PER_ROW = L / OPT; // 1024

__global__ __launch_bounds__(TPB)
void median9_kernel(const float* __restrict__ x, float* __restrict__ y)
{
    int t   = blockIdx.x * TPB + threadIdx.x;
    int row = t >> 10;                            // t / 1024
    int cb  = (t & (THREADS_PER_ROW - 1)) << 4;   // column base, multiple of 16

    const float* rp = x + (size_t)row * L;

    // v[i] = x[row, cb - 4 + i], i in [0, 24). cb-4 is 16B-aligned.
    float v[24];
    if (cb >= 4 && cb + 20 <= L) {
        const float4* p = reinterpret_cast<const float4*>(rp + cb - 4);
        #pragma unroll
        for (int q = 0; q < 6; q++) {
            float4 a = __ldcs(p + q);           // front-batched, MLP=6
            v[4*q + 0] = a.x; v[4*q + 1] = a.y;
            v[4*q + 2] = a.z; v[4*q + 3] = a.w;
        }
    } else {
        #pragma unroll
        for (int i = 0; i < 24; i++) {
            int c = cb - 4 + i;
            v[i] = (c >= 0 && c < L) ? rp[c] : 0.0f;
        }
    }

    float o[16];
    #pragma unroll
    for (int j = 0; j < 8; j++) {
        int b = 2 * j;
        // Shared 8 elements between windows b and b+1: v[b+1 .. b+8]
        float s3, s4;
        rank34_of8(v[b + 1], v[b + 2], v[b + 3], v[b + 4],
                   v[b + 5], v[b + 6], v[b + 7], v[b + 8], s3, s4);
        o[b]     = fminf(fmaxf(v[b],     s3), s4);
        o[b + 1] = fminf(fmaxf(v[b + 9], s3), s4);
    }

    float4* op = reinterpret_cast<float4*>(y + (size_t)row * L + cb);
    __stcs(op + 0, make_float4(o[0],  o[1],  o[2],  o[3]));
    __stcs(op + 1, make_float4(o[4],  o[5],  o[6],  o[7]));
    __stcs(op + 2, make_float4(o[8],  o[9],  o[10], o[11]));
    __stcs(op + 3, make_float4(o[12], o[13], o[14], o[15]));
}

extern "C" void kernel_launch(void* const* d_in, const int* in_sizes, int n_in,
                              void* d_out, int out_size)
{
    const float* x = (const float*)d_in[0];
    float* y = (float*)d_out;

    int total_threads = ROWS * THREADS_PER_ROW;   // 1,048,576
    int blocks = total_threads / TPB;             // 4096
    median9_kernel<<<blocks, TPB>>>(x, y);
}

// round 5
// speedup vs baseline: 1.0887x; 1.0887x over previous
#include <cuda_runtime.h>
#include <cuda_bf16.h>

// MedianFilter1D: x[16, 64, 16384] fp32, window k=9, zero padding.
// 1024 rows x 16384. Each thread: 8 outputs, R2 memory shape (2 own LDG.128,
// shfl halos), __stcs stores, default-cached input (input is replay-invariant
// -> L2-resident).
//
// Round 5 compute scheme (13.5 ops/output vs ~18 for pruned Batcher sort-8):
//   1. sort4 runs of v at odd offsets p in {1,3,5,7,9,11}   (5 CE each)
//   2. per window-pair b: shared-8 = run[b+1] ++ run[b+5]; ranks 3,4 of the
//      union of two sorted-4s via pruned odd-even merge(4,4):
//        e2 = max(max(a0,b0), min(a2,b2))   // rank2 of even-chain merge
//        o1 = min(max(a1,b1), min(a3,b3))   // rank1 of odd-chain merge
//        s3 = min(o1,e2); s4 = max(o1,e2)
//   3. median9(window) = min(max(inserted, s3), s4)

#define CE(a, b) { float _lo = fminf(a, b); float _hi = fmaxf(a, b); (a) = _lo; (b) = _hi; }

__device__ __forceinline__ void sort4(float& x0, float& x1, float& x2, float& x3)
{
    CE(x0, x1) CE(x2, x3) CE(x0, x2) CE(x1, x3) CE(x1, x2)
}

static constexpr int L    = 16384;
static constexpr int ROWS = 16 * 64;           // 1024
static constexpr int TPB  = 256;
static constexpr int THREADS_PER_ROW = L / 8;  // 2048

__global__ __launch_bounds__(TPB)
void median9_kernel(const float* __restrict__ x, float* __restrict__ y)
{
    const unsigned FULL = 0xFFFFFFFFu;
    int t    = blockIdx.x * TPB + threadIdx.x;
    int lane = threadIdx.x & 31;
    int row  = t >> 11;                          // t / 2048
    int cb   = (t & (THREADS_PER_ROW - 1)) << 3; // column base, multiple of 8

    const float* rp = x + (size_t)row * L;

    // Own 8 floats (cols [cb, cb+8)), default-cached: input never changes
    // across graph replays, so L2 residency is pure win.
    float4 lo = *reinterpret_cast<const float4*>(rp + cb);
    float4 hi = *reinterpret_cast<const float4*>(rp + cb + 4);

    // Halos from neighbor lanes.
    float4 lh, rh;
    lh.x = __shfl_up_sync(FULL, hi.x, 1);
    lh.y = __shfl_up_sync(FULL, hi.y, 1);
    lh.z = __shfl_up_sync(FULL, hi.z, 1);
    lh.w = __shfl_up_sync(FULL, hi.w, 1);
    rh.x = __shfl_down_sync(FULL, lo.x, 1);
    rh.y = __shfl_down_sync(FULL, lo.y, 1);
    rh.z = __shfl_down_sync(FULL, lo.z, 1);
    rh.w = __shfl_down_sync(FULL, lo.w, 1);

    if (lane == 0) {
        if (cb > 0) lh = *reinterpret_cast<const float4*>(rp + cb - 4);
        else        lh = make_float4(0.f, 0.f, 0.f, 0.f);
    }
    if (lane == 31) {
        if (cb + 12 <= L) rh = *reinterpret_cast<const float4*>(rp + cb + 8);
        else              rh = make_float4(0.f, 0.f, 0.f, 0.f);
    }

    float v[16];
    v[0]  = lh.x; v[1]  = lh.y; v[2]  = lh.z; v[3]  = lh.w;
    v[4]  = lo.x; v[5]  = lo.y; v[6]  = lo.z; v[7]  = lo.w;
    v[8]  = hi.x; v[9]  = hi.y; v[10] = hi.z; v[11] = hi.w;
    v[12] = rh.x; v[13] = rh.y; v[14] = rh.z; v[15] = rh.w;

    // Sorted 4-runs at odd offsets 1,3,5,7,9,11. R[i] = sorted(v[2i+1 .. 2i+5)).
    float R[6][4];
    #pragma unroll
    for (int i = 0; i < 6; i++) {
        int p = 2 * i + 1;
        float x0 = v[p], x1 = v[p + 1], x2 = v[p + 2], x3 = v[p + 3];
        sort4(x0, x1, x2, x3);
        R[i][0] = x0; R[i][1] = x1; R[i][2] = x2; R[i][3] = x3;
    }

    float o[8];
    #pragma unroll
    for (int j = 0; j < 4; j++) {
        int b = 2 * j;
        const float* A = R[j];       // sorted v[b+1 .. b+5)
        const float* B = R[j + 2];   // sorted v[b+5 .. b+9)
        float e2 = fmaxf(fmaxf(A[0], B[0]), fminf(A[2], B[2]));
        float o1 = fminf(fmaxf(A[1], B[1]), fminf(A[3], B[3]));
        float s3 = fminf(o1, e2);
        float s4 = fmaxf(o1, e2);
        o[b]     = fminf(fmaxf(v[b],     s3), s4);
        o[b + 1] = fminf(fmaxf(v[b + 9], s3), s4);
    }

    float4* op = reinterpret_cast<float4*>(y + (size_t)row * L + cb);
    __stcs(op,     make_float4(o[0], o[1], o[2], o[3]));
    __stcs(op + 1, make_float4(o[4], o[5], o[6], o[7]));
}

extern "C" void kernel_launch(void* const* d_in, const int* in_sizes, int n_in,
                              void* d_out, int out_size)
{
    const float* x = (const float*)d_in[0];
    float* y = (float*)d_out;

    int total_threads = ROWS * THREADS_PER_ROW;   // 2,097,152
    int blocks = total_threads / TPB;             // 8192
    median9_kernel<<<blocks, TPB>>>(x, y);
}

// round 7
// speedup vs baseline: 1.0972x; 1.0078x over previous
#include <cuda_runtime.h>
#include <cuda_bf16.h>

// MedianFilter1D: x[16, 64, 16384] fp32, window k=9, zero padding.
// 1024 rows x 16384. Each thread: 8 outputs via ONE 256-bit load/store.
//
// Round 7 — L2 residency management (R6 retry; sm_103a ptxas requires
// .v8.b32 width for L2::evict_* modifiers).
// Replay loop is HBM-traffic bound: 134 MB (67 in + 67 out) per replay at
// ~5.5 TB/s achievable = 24.3 us harness period. Input is replay-invariant
// and fits in the 126 MB L2; output evicts it without hints. Fix:
//   input:  ld.global.nc.L2::evict_last.v8.b32  (pin input across replays)
//   output: st.global.L2::evict_first.v8.b32    (output recycles own lines)
//
// Compute: sorted 4-runs + pruned odd-even merge(4,4) -> ranks 3,4 of the
// shared 8; median9 = min(max(inserted, s3), s4).

#define CE(a, b) { float _lo = fminf(a, b); float _hi = fmaxf(a, b); (a) = _lo; (b) = _hi; }

__device__ __forceinline__ void sort4(float& x0, float& x1, float& x2, float& x3)
{
    CE(x0, x1) CE(x2, x3) CE(x0, x2) CE(x1, x3) CE(x1, x2)
}

// 256-bit input load, L2 evict-last (input is replay-invariant).
__device__ __forceinline__ void ld_in8(const float* p, float* v)
{
    asm volatile(
        "ld.global.nc.L2::evict_last.v8.f32 {%0,%1,%2,%3,%4,%5,%6,%7}, [%8];"
        : "=f"(v[0]), "=f"(v[1]), "=f"(v[2]), "=f"(v[3]),
          "=f"(v[4]), "=f"(v[5]), "=f"(v[6]), "=f"(v[7])
        : "l"(p));
}

// 256-bit output store, L2 evict-first (write-once, must not displace input).
__device__ __forceinline__ void st_out8(float* p, const float* o)
{
    asm volatile(
        "st.global.L2::evict_first.v8.f32 [%0], {%1,%2,%3,%4,%5,%6,%7,%8};"
        :: "l"(p),
           "f"(o[0]), "f"(o[1]), "f"(o[2]), "f"(o[3]),
           "f"(o[4]), "f"(o[5]), "f"(o[6]), "f"(o[7])
        : "memory");
}

static constexpr int L    = 16384;
static constexpr int ROWS = 16 * 64;           // 1024
static constexpr int TPB  = 256;
static constexpr int THREADS_PER_ROW = L / 8;  // 2048

__global__ __launch_bounds__(TPB)
void median9_kernel(const float* __restrict__ x, float* __restrict__ y)
{
    const unsigned FULL = 0xFFFFFFFFu;
    int t    = blockIdx.x * TPB + threadIdx.x;
    int lane = threadIdx.x & 31;
    int row  = t >> 11;                          // t / 2048
    int cb   = (t & (THREADS_PER_ROW - 1)) << 3; // column base, multiple of 8

    const float* rp = x + (size_t)row * L;

    float v[16];
    // Own 8 floats -> v[4..12), one LDG.256 (32B-aligned since cb % 8 == 0).
    ld_in8(rp + cb, v + 4);

    // Halos from neighbor lanes.
    float4 lh, rh;
    lh.x = __shfl_up_sync(FULL, v[8],  1);
    lh.y = __shfl_up_sync(FULL, v[9],  1);
    lh.z = __shfl_up_sync(FULL, v[10], 1);
    lh.w = __shfl_up_sync(FULL, v[11], 1);
    rh.x = __shfl_down_sync(FULL, v[4], 1);
    rh.y = __shfl_down_sync(FULL, v[5], 1);
    rh.z = __shfl_down_sync(FULL, v[6], 1);
    rh.w = __shfl_down_sync(FULL, v[7], 1);

    // Warp-edge fixups (cross-warp halo or zero padding).
    if (lane == 0) {
        if (cb > 0) lh = __ldg(reinterpret_cast<const float4*>(rp + cb - 4));
        else        lh = make_float4(0.f, 0.f, 0.f, 0.f);
    }
    if (lane == 31) {
        if (cb + 12 <= L) rh = __ldg(reinterpret_cast<const float4*>(rp + cb + 8));
        else              rh = make_float4(0.f, 0.f, 0.f, 0.f);
    }

    v[0]  = lh.x; v[1]  = lh.y; v[2]  = lh.z; v[3]  = lh.w;
    v[12] = rh.x; v[13] = rh.y; v[14] = rh.z; v[15] = rh.w;

    // Sorted 4-runs at odd offsets 1,3,5,7,9,11.
    float R[6][4];
    #pragma unroll
    for (int i = 0; i < 6; i++) {
        int p = 2 * i + 1;
        float x0 = v[p], x1 = v[p + 1], x2 = v[p + 2], x3 = v[p + 3];
        sort4(x0, x1, x2, x3);
        R[i][0] = x0; R[i][1] = x1; R[i][2] = x2; R[i][3] = x3;
    }

    float o[8];
    #pragma unroll
    for (int j = 0; j < 4; j++) {
        int b = 2 * j;
        const float* A = R[j];       // sorted v[b+1 .. b+5)
        const float* B = R[j + 2];   // sorted v[b+5 .. b+9)
        float e2 = fmaxf(fmaxf(A[0], B[0]), fminf(A[2], B[2]));
        float o1 = fminf(fmaxf(A[1], B[1]), fminf(A[3], B[3]));
        float s3 = fminf(o1, e2);
        float s4 = fmaxf(o1, e2);
        o[b]     = fminf(fmaxf(v[b],     s3), s4);
        o[b + 1] = fminf(fmaxf(v[b + 9], s3), s4);
    }

    st_out8(y + (size_t)row * L + cb, o);
}

extern "C" void kernel_launch(void* const* d_in, const int* in_sizes, int n_in,
                              void* d_out, int out_size)
{
    const float* x = (const float*)d_in[0];
    float* y = (float*)d_out;

    int total_threads = ROWS * THREADS_PER_ROW;   // 2,097,152
    int blocks = total_threads / TPB;             // 8192
    median9_kernel<<<blocks, TPB>>>(x, y);
}

// round 8
// speedup vs baseline: 1.1764x; 1.0722x over previous
#include <cuda_runtime.h>
#include <cuda_bf16.h>

// MedianFilter1D: x[16, 64, 16384] fp32, window k=9, zero padding.
// 1024 rows x 16384 = 2,097,152 chunks of 8 outputs.
//
// Round 8 — software-pipelined grid-stride loop. R7 profile: DRAM busy 49%
// + ALU busy 53%, kernel = their SUM -> the pipes alternate (load burst,
// wait, compute) instead of overlapping. Fix: each thread handles 4 chunks
// (grid-strided so every LDG.256 stays perfectly warp-coalesced), double
// buffered in registers: load chunk i+1 is in flight while computing chunk i.
//
// Compute (90 ops / 8 outputs): sort 7 adjacent pairs once; each sorted-4 run
// = 3-CE merge of two sorted pairs; ranks 3,4 of each window-pair's shared 8
// via pruned odd-even merge(4,4); median9 = clamp(inserted, s3, s4).
//
// Flat-address identity: chunk c covers flat elements [8c, 8c+8); row
// boundaries only matter for halos (c%2048 == 0 or 2047).

#define CE(a, b) { float _lo = fminf(a, b); float _hi = fmaxf(a, b); (a) = _lo; (b) = _hi; }

__device__ __forceinline__ void ld_in8(const float* p, float* v)
{
    asm volatile(
        "ld.global.nc.L2::evict_last.v8.f32 {%0,%1,%2,%3,%4,%5,%6,%7}, [%8];"
        : "=f"(v[0]), "=f"(v[1]), "=f"(v[2]), "=f"(v[3]),
          "=f"(v[4]), "=f"(v[5]), "=f"(v[6]), "=f"(v[7])
        : "l"(p));
}

__device__ __forceinline__ void st_out8(float* p, const float* o)
{
    asm volatile(
        "st.global.L2::evict_first.v8.f32 [%0], {%1,%2,%3,%4,%5,%6,%7,%8};"
        :: "l"(p),
           "f"(o[0]), "f"(o[1]), "f"(o[2]), "f"(o[3]),
           "f"(o[4]), "f"(o[5]), "f"(o[6]), "f"(o[7])
        : "memory");
}

static constexpr int L       = 16384;
static constexpr int ROWS    = 16 * 64;
static constexpr int TPB     = 256;
static constexpr int NCHUNK  = ROWS * (L / 8);        // 2,097,152
static constexpr int GRID    = 2048;
static constexpr int STRIDE  = GRID * TPB;            // 524,288 threads
static constexpr int ITERS   = NCHUNK / STRIDE;       // 4

__device__ __forceinline__ void process_chunk(
    const float* __restrict__ x, float* __restrict__ y,
    const float* own, int c, int lane)
{
    const unsigned FULL = 0xFFFFFFFFu;
    float v[16];
    #pragma unroll
    for (int i = 0; i < 8; i++) v[4 + i] = own[i];

    // Halos from neighbor lanes (consecutive c across lanes).
    float4 lh, rh;
    lh.x = __shfl_up_sync(FULL, v[8],  1);
    lh.y = __shfl_up_sync(FULL, v[9],  1);
    lh.z = __shfl_up_sync(FULL, v[10], 1);
    lh.w = __shfl_up_sync(FULL, v[11], 1);
    rh.x = __shfl_down_sync(FULL, v[4], 1);
    rh.y = __shfl_down_sync(FULL, v[5], 1);
    rh.z = __shfl_down_sync(FULL, v[6], 1);
    rh.w = __shfl_down_sync(FULL, v[7], 1);

    int cm = c & 2047;   // chunk position within its row
    if (lane == 0) {
        if (cm != 0) lh = __ldg(reinterpret_cast<const float4*>(x + 8 * (size_t)c - 4));
        else         lh = make_float4(0.f, 0.f, 0.f, 0.f);
    }
    if (lane == 31) {
        if (cm != 2047) rh = __ldg(reinterpret_cast<const float4*>(x + 8 * (size_t)c + 8));
        else            rh = make_float4(0.f, 0.f, 0.f, 0.f);
    }
    v[0]  = lh.x; v[1]  = lh.y; v[2]  = lh.z; v[3]  = lh.w;
    v[12] = rh.x; v[13] = rh.y; v[14] = rh.z; v[15] = rh.w;

    // Sorted pairs P_j = sorted(v[2j+1], v[2j+2]), j = 0..6.
    float pl[7], ph[7];
    #pragma unroll
    for (int j = 0; j < 7; j++) {
        pl[j] = fminf(v[2*j + 1], v[2*j + 2]);
        ph[j] = fmaxf(v[2*j + 1], v[2*j + 2]);
    }

    // Runs R[i] = sorted-4 of v[2i+1 .. 2i+5) = merge(P_i, P_{i+1}), 3 CE.
    float R[6][4];
    #pragma unroll
    for (int i = 0; i < 6; i++) {
        float x0 = pl[i], x1 = ph[i], x2 = pl[i + 1], x3 = ph[i + 1];
        CE(x0, x2) CE(x1, x3) CE(x1, x2)
        R[i][0] = x0; R[i][1] = x1; R[i][2] = x2; R[i][3] = x3;
    }

    float o[8];
    #pragma unroll
    for (int j = 0; j < 4; j++) {
        int b = 2 * j;
        const float* A = R[j];       // sorted v[b+1 .. b+5)
        const float* B = R[j + 2];   // sorted v[b+5 .. b+9)
        float e2 = fmaxf(fmaxf(A[0], B[0]), fminf(A[2], B[2]));
        float o1 = fminf(fmaxf(A[1], B[1]), fminf(A[3], B[3]));
        float s3 = fminf(o1, e2);
        float s4 = fmaxf(o1, e2);
        o[b]     = fminf(fmaxf(v[b],     s3), s4);
        o[b + 1] = fminf(fmaxf(v[b + 9], s3), s4);
    }

    st_out8(y + 8 * (size_t)c, o);
}

__global__ __launch_bounds__(TPB)
void median9_kernel(const float* __restrict__ x, float* __restrict__ y)
{
    int t    = blockIdx.x * TPB + threadIdx.x;
    int lane = threadIdx.x & 31;

    float A[8], B[8];
    int c = t;
    ld_in8(x + 8 * (size_t)c, A);                 // prologue load

    static_assert(ITERS == 4, "pipeline is hand-unrolled for 4 iterations");

    ld_in8(x + 8 * (size_t)(c + STRIDE), B);      // load #1 in flight
    process_chunk(x, y, A, c, lane);              // compute #0
    c += STRIDE;

    ld_in8(x + 8 * (size_t)(c + STRIDE), A);      // load #2 in flight
    process_chunk(x, y, B, c, lane);              // compute #1
    c += STRIDE;

    ld_in8(x + 8 * (size_t)(c + STRIDE), B);      // load #3 in flight
    process_chunk(x, y, A, c, lane);              // compute #2
    c += STRIDE;

    process_chunk(x, y, B, c, lane);              // compute #3
}

extern "C" void kernel_launch(void* const* d_in, const int* in_sizes, int n_in,
                              void* d_out, int out_size)
{
    const float* x = (const float*)d_in[0];
    float* y = (float*)d_out;
    median9_kernel<<<GRID, TPB>>>(x, y);
}